// round 1
// baseline (speedup 1.0000x reference)
#include <cuda_runtime.h>

#define T_TOK 16384
#define NE 8
#define NK 2

// ---------------- scratch (device globals; no allocation allowed) ----------------
__device__ int   g_maskmode;                 // 1 = mask is 1-byte bool, 0 = int32
__device__ int   g_cnt[3][16];               // per stage, per (slot*8+expert)
__device__ int   g_tok[3][16][T_TOK];
__device__ float g_wgt[3][16][T_TOK];
__device__ float g_h1a[T_TOK * 256];
__device__ float g_h1b[T_TOK * 256];
__device__ float g_h2a[T_TOK * 256];
__device__ float g_h2b[T_TOK * 256];
__device__ float g_h3a[T_TOK * 512];
__device__ float g_h3b[T_TOK * 512];

// ---------------- mask dtype detection ----------------
// Reads only the first 256 KB (valid under both bool and int32 storage).
// Under byte interpretation, one-hot property (sum over e == 1 per (k,t))
// must hold for every sampled token; under int32 storage it fails.
__global__ void detect_mask(const unsigned char* __restrict__ m) {
    __shared__ int bad;
    if (threadIdx.x == 0) bad = 0;
    __syncthreads();
    int t = threadIdx.x;  // 256 sampled tokens
    #pragma unroll
    for (int k = 0; k < NK; k++) {
        int s = 0;
        #pragma unroll
        for (int e = 0; e < NE; e++)
            s += (m[(e * NK + k) * T_TOK + t] != 0) ? 1 : 0;
        if (s != 1) bad = 1;
    }
    __syncthreads();
    if (threadIdx.x == 0) g_maskmode = bad ? 0 : 1;
}

__global__ void zero_cnt() {
    if (threadIdx.x < 48) ((int*)g_cnt)[threadIdx.x] = 0;
}

// ---------------- routing: build per-(stage,slot,expert) token lists ----------------
__global__ void route3(const unsigned char* __restrict__ m1,
                       const unsigned char* __restrict__ m2,
                       const unsigned char* __restrict__ m3,
                       const float* __restrict__ r1,
                       const float* __restrict__ r2,
                       const float* __restrict__ r3) {
    int tid = blockIdx.x * blockDim.x + threadIdx.x;
    if (tid >= 3 * NK * T_TOK) return;
    int s   = tid / (NK * T_TOK);
    int rem = tid % (NK * T_TOK);
    int k   = rem / T_TOK;
    int t   = rem % T_TOK;
    const unsigned char* m = (s == 0) ? m1 : (s == 1) ? m2 : m3;
    const float*         r = (s == 0) ? r1 : (s == 1) ? r2 : r3;

    int e = 0;
    if (g_maskmode) {
        #pragma unroll
        for (int i = 0; i < NE; i++)
            if (m[(i * NK + k) * T_TOK + t]) e = i;
    } else {
        const int* mi = (const int*)m;
        #pragma unroll
        for (int i = 0; i < NE; i++)
            if (mi[(i * NK + k) * T_TOK + t]) e = i;
    }
    float w = r[t * NK + k];
    int g = k * NE + e;
    int p = atomicAdd(&g_cnt[s][g], 1);
    g_tok[s][g][p] = t;
    g_wgt[s][g][p] = w;
}

// ---------------- gathered expert GEMM ----------------
// C[gathered rows, OUT] = A[tok,:] @ W_e^T  (+bias, optional relu, * routing weight)
// Block: 64x64 tile, BK=16, 256 threads, 4x4 micro-tile.
template <int STAGE, int IN, int OUT, bool RELU>
__global__ __launch_bounds__(256)
void moe_gemm(const float* __restrict__ X,
              const float* __restrict__ W,
              const float* __restrict__ Bias) {
    const float *A0, *A1;
    float *O0, *O1;
    if constexpr (STAGE == 0) { A0 = X;     A1 = nullptr; O0 = g_h1a; O1 = g_h1b; }
    else if constexpr (STAGE == 1) { A0 = g_h1a; A1 = g_h1b; O0 = g_h2a; O1 = g_h2b; }
    else { A0 = g_h2a; A1 = g_h2b; O0 = g_h3a; O1 = g_h3b; }
    constexpr bool SUMIN = (STAGE != 0);

    const int g  = blockIdx.z;               // slot*8 + expert
    const int n  = g_cnt[STAGE][g];
    const int m0 = blockIdx.x * 64;
    if (m0 >= n) return;
    const int e  = g & 7;
    const int n0 = blockIdx.y * 64;
    float* Out = (g >= 8) ? O1 : O0;

    __shared__ float As[16][68];
    __shared__ float Bs[16][68];
    __shared__ int   s_tok[64];
    __shared__ float s_w[64];

    const int tid = threadIdx.x;
    if (tid < 64) {
        int gi = m0 + tid;
        int src = (gi < n) ? gi : (n - 1);   // clamp: loads valid data, store masked
        s_tok[tid] = g_tok[STAGE][g][src];
        s_w[tid]   = (gi < n) ? g_wgt[STAGE][g][src] : 0.0f;
    }
    __syncthreads();

    const float* We = W + (size_t)e * OUT * IN;
    const int ldi = tid & 15;   // k within tile
    const int ldr = tid >> 4;   // row/col base (0..15)
    const int ty  = tid >> 4;
    const int tx  = tid & 15;

    float acc[4][4] = {};

    for (int kb = 0; kb < IN; kb += 16) {
        #pragma unroll
        for (int r = 0; r < 4; r++) {
            int i = ldr + r * 16;
            int t = s_tok[i];
            float v;
            if constexpr (SUMIN)
                v = A0[(size_t)t * IN + kb + ldi] + A1[(size_t)t * IN + kb + ldi];
            else
                v = A0[(size_t)t * IN + kb + ldi];
            As[ldi][i] = v;
        }
        #pragma unroll
        for (int r = 0; r < 4; r++) {
            int j = ldr + r * 16;
            Bs[ldi][j] = We[(size_t)(n0 + j) * IN + kb + ldi];
        }
        __syncthreads();

        #pragma unroll
        for (int kk = 0; kk < 16; kk++) {
            float4 a = *(const float4*)(&As[kk][ty * 4]);
            float4 b = *(const float4*)(&Bs[kk][tx * 4]);
            acc[0][0] += a.x * b.x; acc[0][1] += a.x * b.y; acc[0][2] += a.x * b.z; acc[0][3] += a.x * b.w;
            acc[1][0] += a.y * b.x; acc[1][1] += a.y * b.y; acc[1][2] += a.y * b.z; acc[1][3] += a.y * b.w;
            acc[2][0] += a.z * b.x; acc[2][1] += a.z * b.y; acc[2][2] += a.z * b.z; acc[2][3] += a.z * b.w;
            acc[3][0] += a.w * b.x; acc[3][1] += a.w * b.y; acc[3][2] += a.w * b.z; acc[3][3] += a.w * b.w;
        }
        __syncthreads();
    }

    float4 bias = *(const float4*)&Bias[e * OUT + n0 + tx * 4];
    #pragma unroll
    for (int i = 0; i < 4; i++) {
        int tr = ty * 4 + i;
        int gi = m0 + tr;
        if (gi >= n) continue;
        int   t = s_tok[tr];
        float w = s_w[tr];
        float4 v;
        v.x = acc[i][0] + bias.x;
        v.y = acc[i][1] + bias.y;
        v.z = acc[i][2] + bias.z;
        v.w = acc[i][3] + bias.w;
        if constexpr (RELU) {
            v.x = fmaxf(v.x, 0.0f); v.y = fmaxf(v.y, 0.0f);
            v.z = fmaxf(v.z, 0.0f); v.w = fmaxf(v.w, 0.0f);
        }
        v.x *= w; v.y *= w; v.z *= w; v.w *= w;
        *(float4*)&Out[(size_t)t * OUT + n0 + tx * 4] = v;
    }
}

// ---------------- final combine + relu ----------------
__global__ void finalize(float* __restrict__ out) {
    int i = blockIdx.x * blockDim.x + threadIdx.x;  // over T*512/4 float4s
    float4 a = ((const float4*)g_h3a)[i];
    float4 b = ((const float4*)g_h3b)[i];
    float4 v;
    v.x = fmaxf(a.x + b.x, 0.0f);
    v.y = fmaxf(a.y + b.y, 0.0f);
    v.z = fmaxf(a.z + b.z, 0.0f);
    v.w = fmaxf(a.w + b.w, 0.0f);
    ((float4*)out)[i] = v;
}

// ---------------- launch ----------------
extern "C" void kernel_launch(void* const* d_in, const int* in_sizes, int n_in,
                              void* d_out, int out_size) {
    const float*         x  = (const float*)d_in[0];
    const unsigned char* m1 = (const unsigned char*)d_in[1];
    const unsigned char* m2 = (const unsigned char*)d_in[2];
    const unsigned char* m3 = (const unsigned char*)d_in[3];
    const float*         r1 = (const float*)d_in[4];
    const float*         r2 = (const float*)d_in[5];
    const float*         r3 = (const float*)d_in[6];
    const float*         W1 = (const float*)d_in[7];
    const float*         b1 = (const float*)d_in[8];
    const float*         W2 = (const float*)d_in[9];
    const float*         b2 = (const float*)d_in[10];
    const float*         W3 = (const float*)d_in[11];
    const float*         b3 = (const float*)d_in[12];
    float* out = (float*)d_out;

    detect_mask<<<1, 256>>>(m1);
    zero_cnt<<<1, 64>>>();
    route3<<<(3 * NK * T_TOK + 255) / 256, 256>>>(m1, m2, m3, r1, r2, r3);

    dim3 g1(T_TOK / 64, 256 / 64, 16);
    dim3 g2(T_TOK / 64, 256 / 64, 16);
    dim3 g3(T_TOK / 64, 512 / 64, 16);
    moe_gemm<0, 512, 256, false><<<g1, 256>>>(x, W1, b1);
    moe_gemm<1, 256, 256, false><<<g2, 256>>>(nullptr, W2, b2);
    moe_gemm<2, 256, 512, true ><<<g3, 256>>>(nullptr, W3, b3);

    finalize<<<(T_TOK * 512 / 4) / 256, 256>>>(out);
}

// round 3
// speedup vs baseline: 2.6153x; 2.6153x over previous
#include <cuda_runtime.h>
#include <cstdint>

#define T_TOK 16384
#define NE 8
#define NK 2

// ---------------- scratch (device globals; no allocation allowed) ----------------
__device__ int   g_maskmode;                 // 1 = mask is 1-byte bool, 0 = int32
__device__ int   g_cnt[3][16];               // per stage, per (slot*8+expert)
__device__ int   g_tok[3][16][T_TOK];
__device__ float g_wgt[3][16][T_TOK];
__device__ float g_h1a[T_TOK * 256];
__device__ float g_h1b[T_TOK * 256];
__device__ float g_h2a[T_TOK * 256];
__device__ float g_h2b[T_TOK * 256];
__device__ float g_h3a[T_TOK * 512];
__device__ float g_h3b[T_TOK * 512];

// ---------------- helpers ----------------
__device__ __forceinline__ uint32_t f2tf(float f) {
    uint32_t u; asm("cvt.rn.tf32.f32 %0, %1;" : "=r"(u) : "f"(f)); return u;
}

// D = A(16x8,row) * B(8x8,col) + D, tf32 in, f32 accum.  (sm_80+, valid on sm_103)
__device__ __forceinline__ void mma8(float* c, const uint32_t* a,
                                     uint32_t b0, uint32_t b1) {
    asm volatile(
        "mma.sync.aligned.m16n8k8.row.col.f32.tf32.tf32.f32 "
        "{%0,%1,%2,%3}, {%4,%5,%6,%7}, {%8,%9}, {%0,%1,%2,%3};"
        : "+f"(c[0]), "+f"(c[1]), "+f"(c[2]), "+f"(c[3])
        : "r"(a[0]), "r"(a[1]), "r"(a[2]), "r"(a[3]), "r"(b0), "r"(b1));
}

// ---------------- mask dtype detection ----------------
__global__ void detect_mask(const unsigned char* __restrict__ m) {
    __shared__ int bad;
    if (threadIdx.x == 0) bad = 0;
    __syncthreads();
    int t = threadIdx.x;
    #pragma unroll
    for (int k = 0; k < NK; k++) {
        int s = 0;
        #pragma unroll
        for (int e = 0; e < NE; e++)
            s += (m[(e * NK + k) * T_TOK + t] != 0) ? 1 : 0;
        if (s != 1) bad = 1;
    }
    __syncthreads();
    if (threadIdx.x == 0) g_maskmode = bad ? 0 : 1;
}

__global__ void zero_cnt() {
    if (threadIdx.x < 48) ((int*)g_cnt)[threadIdx.x] = 0;
}

// ---------------- routing ----------------
__global__ void route3(const unsigned char* __restrict__ m1,
                       const unsigned char* __restrict__ m2,
                       const unsigned char* __restrict__ m3,
                       const float* __restrict__ r1,
                       const float* __restrict__ r2,
                       const float* __restrict__ r3) {
    int tid = blockIdx.x * blockDim.x + threadIdx.x;
    if (tid >= 3 * NK * T_TOK) return;
    int s   = tid / (NK * T_TOK);
    int rem = tid % (NK * T_TOK);
    int k   = rem / T_TOK;
    int t   = rem % T_TOK;
    const unsigned char* m = (s == 0) ? m1 : (s == 1) ? m2 : m3;
    const float*         r = (s == 0) ? r1 : (s == 1) ? r2 : r3;

    int e = 0;
    if (g_maskmode) {
        #pragma unroll
        for (int i = 0; i < NE; i++)
            if (m[(i * NK + k) * T_TOK + t]) e = i;
    } else {
        const int* mi = (const int*)m;
        #pragma unroll
        for (int i = 0; i < NE; i++)
            if (mi[(i * NK + k) * T_TOK + t]) e = i;
    }
    float w = r[t * NK + k];
    int g = k * NE + e;
    int p = atomicAdd(&g_cnt[s][g], 1);
    g_tok[s][g][p] = t;
    g_wgt[s][g][p] = w;
}

// ---------------- tf32 mma.sync gathered expert GEMM ----------------
// BM=128, BN=128, BK=16 (2 k8 steps), 256 threads, 8 warps (2m x 4n), warp 64x32.
// Smem in fragment-native layout [step][tile][lane^step][reg] -> lds.128 frags.
template <int STAGE, int IN, int OUT, bool RELU>
__global__ __launch_bounds__(256, 2)
void moe_mma(const float* __restrict__ X,
             const float* __restrict__ W,
             const float* __restrict__ Bias) {
    const float *A0, *A1;
    float *O0, *O1;
    if constexpr (STAGE == 0)      { A0 = X;     A1 = nullptr; O0 = g_h1a; O1 = g_h1b; }
    else if constexpr (STAGE == 1) { A0 = g_h1a; A1 = g_h1b;   O0 = g_h2a; O1 = g_h2b; }
    else                           { A0 = g_h2a; A1 = g_h2b;   O0 = g_h3a; O1 = g_h3b; }
    constexpr bool SUMIN = (STAGE != 0);

    const int g  = blockIdx.z;                 // slot*8 + expert
    const int n  = g_cnt[STAGE][g];
    const int m0 = blockIdx.x * 128;
    if (m0 >= n) return;
    const int e  = g & 7;
    const int n0 = blockIdx.y * 128;
    float* Out = (g >= 8) ? O1 : O0;

    // fragment-layout smem: [buf][step2][tile8][lane32][reg4] floats
    __shared__ float sA[2][2 * 8 * 32 * 4];
    __shared__ float sB[2][2 * 8 * 32 * 4];
    __shared__ int   s_tok[128];
    __shared__ float s_w[128];

    const int tid  = threadIdx.x;
    const int wid  = tid >> 5;
    const int lane = tid & 31;
    const int wm   = wid >> 2;   // 0..1
    const int wn   = wid & 3;    // 0..3

    if (tid < 128) {
        int gi  = m0 + tid;
        int src = (gi < n) ? gi : (n - 1);
        s_tok[tid] = g_tok[STAGE][g][src];
        s_w[tid]   = (gi < n) ? g_wgt[STAGE][g][src] : 0.0f;
    }
    __syncthreads();

    const float* We = W + (size_t)e * OUT * IN;

    float c[4][4][4];
    #pragma unroll
    for (int a = 0; a < 4; a++)
        #pragma unroll
        for (int b = 0; b < 4; b++)
            #pragma unroll
            for (int d = 0; d < 4; d++) c[a][b][d] = 0.0f;

    float4 va[2], vb[2];

    // --- load one BK=16 chunk into registers (gather A, stream B) ---
    auto LOAD = [&](int kb) {
        #pragma unroll
        for (int it = 0; it < 2; it++) {
            int idx = tid + it * 256;          // 0..511
            int row = idx >> 2;                // 0..127
            int j   = idx & 3;                 // k-group of 4
            int t = s_tok[row];
            float4 v = *(const float4*)(A0 + (size_t)t * IN + kb + j * 4);
            if constexpr (SUMIN) {
                float4 v2 = *(const float4*)(A1 + (size_t)t * IN + kb + j * 4);
                v.x += v2.x; v.y += v2.y; v.z += v2.z; v.w += v2.w;
            }
            va[it] = v;
            vb[it] = *(const float4*)(We + (size_t)(n0 + row) * IN + kb + j * 4);
        }
    };

    // --- convert to tf32 and store into fragment layout ---
    auto STS = [&](int buf) {
        #pragma unroll
        for (int it = 0; it < 2; it++) {
            int idx  = tid + it * 256;
            int row  = idx >> 2;
            int j    = idx & 3;
            int step = j >> 1;
            int h    = j & 1;
            int lane0 = 4 * (row & 7);
            uint32_t ua[4] = { f2tf(va[it].x), f2tf(va[it].y),
                               f2tf(va[it].z), f2tf(va[it].w) };
            uint32_t ub[4] = { f2tf(vb[it].x), f2tf(vb[it].y),
                               f2tf(vb[it].z), f2tf(vb[it].w) };
            // A: mt tile, reg = 2h + row-bit3
            {
                int mt  = row >> 4;
                int reg = 2 * h + ((row >> 3) & 1);
                float* p = &sA[buf][(step * 8 + mt) * 128 + reg];
                #pragma unroll
                for (int i = 0; i < 4; i++)
                    p[((lane0 + i) ^ step) * 4] = __uint_as_float(ua[i]);
            }
            // B: ntp tile pair, reg = 2*(nt&1) + h
            {
                int nt  = row >> 3;
                int ntp = nt >> 1;
                int reg = 2 * (nt & 1) + h;
                float* p = &sB[buf][(step * 8 + ntp) * 128 + reg];
                #pragma unroll
                for (int i = 0; i < 4; i++)
                    p[((lane0 + i) ^ step) * 4] = __uint_as_float(ub[i]);
            }
        }
    };

    // --- compute one chunk from smem ---
    auto COMP = [&](int buf) {
        const uint4* A4 = (const uint4*)sA[buf];
        const uint4* B4 = (const uint4*)sB[buf];
        #pragma unroll
        for (int s = 0; s < 2; s++) {
            int ls = lane ^ s;
            uint4 a[4], bf[2];
            #pragma unroll
            for (int mi = 0; mi < 4; mi++)
                a[mi] = A4[(s * 8 + wm * 4 + mi) * 32 + ls];
            bf[0] = B4[(s * 8 + wn * 2 + 0) * 32 + ls];
            bf[1] = B4[(s * 8 + wn * 2 + 1) * 32 + ls];
            #pragma unroll
            for (int mi = 0; mi < 4; mi++) {
                mma8(c[mi][0], (const uint32_t*)&a[mi], bf[0].x, bf[0].y);
                mma8(c[mi][1], (const uint32_t*)&a[mi], bf[0].z, bf[0].w);
                mma8(c[mi][2], (const uint32_t*)&a[mi], bf[1].x, bf[1].y);
                mma8(c[mi][3], (const uint32_t*)&a[mi], bf[1].z, bf[1].w);
            }
        }
    };

    constexpr int NC = IN / 16;
    LOAD(0);
    STS(0);
    __syncthreads();
    for (int ch = 0; ch < NC; ch++) {
        if (ch + 1 < NC) LOAD((ch + 1) * 16);
        COMP(ch & 1);
        if (ch + 1 < NC) {
            STS((ch + 1) & 1);
            __syncthreads();
        }
    }

    // --- epilogue: bias (+relu) * routing weight, scatter by token ---
    float2 bias[4];
    #pragma unroll
    for (int nt = 0; nt < 4; nt++)
        bias[nt] = *(const float2*)&Bias[e * OUT + n0 + wn * 32 + nt * 8 + (lane & 3) * 2];

    #pragma unroll
    for (int mi = 0; mi < 4; mi++) {
        #pragma unroll
        for (int half = 0; half < 2; half++) {
            int r  = wm * 64 + mi * 16 + (lane >> 2) + half * 8;
            int gi = m0 + r;
            if (gi >= n) continue;
            int   t = s_tok[r];
            float w = s_w[r];
            #pragma unroll
            for (int nt = 0; nt < 4; nt++) {
                float2 v;
                v.x = c[mi][nt][half * 2 + 0] + bias[nt].x;
                v.y = c[mi][nt][half * 2 + 1] + bias[nt].y;
                if constexpr (RELU) {
                    v.x = fmaxf(v.x, 0.0f);
                    v.y = fmaxf(v.y, 0.0f);
                }
                v.x *= w; v.y *= w;
                *(float2*)&Out[(size_t)t * OUT + n0 + wn * 32 + nt * 8 + (lane & 3) * 2] = v;
            }
        }
    }
}

// ---------------- final combine + relu ----------------
__global__ void finalize(float* __restrict__ out) {
    int i = blockIdx.x * blockDim.x + threadIdx.x;
    float4 a = ((const float4*)g_h3a)[i];
    float4 b = ((const float4*)g_h3b)[i];
    float4 v;
    v.x = fmaxf(a.x + b.x, 0.0f);
    v.y = fmaxf(a.y + b.y, 0.0f);
    v.z = fmaxf(a.z + b.z, 0.0f);
    v.w = fmaxf(a.w + b.w, 0.0f);
    ((float4*)out)[i] = v;
}

// ---------------- launch ----------------
extern "C" void kernel_launch(void* const* d_in, const int* in_sizes, int n_in,
                              void* d_out, int out_size) {
    const float*         x  = (const float*)d_in[0];
    const unsigned char* m1 = (const unsigned char*)d_in[1];
    const unsigned char* m2 = (const unsigned char*)d_in[2];
    const unsigned char* m3 = (const unsigned char*)d_in[3];
    const float*         r1 = (const float*)d_in[4];
    const float*         r2 = (const float*)d_in[5];
    const float*         r3 = (const float*)d_in[6];
    const float*         W1 = (const float*)d_in[7];
    const float*         b1 = (const float*)d_in[8];
    const float*         W2 = (const float*)d_in[9];
    const float*         b2 = (const float*)d_in[10];
    const float*         W3 = (const float*)d_in[11];
    const float*         b3 = (const float*)d_in[12];
    float* out = (float*)d_out;

    detect_mask<<<1, 256>>>(m1);
    zero_cnt<<<1, 64>>>();
    route3<<<(3 * NK * T_TOK + 255) / 256, 256>>>(m1, m2, m3, r1, r2, r3);

    dim3 g1(T_TOK / 128, 256 / 128, 16);
    dim3 g2(T_TOK / 128, 256 / 128, 16);
    dim3 g3(T_TOK / 128, 512 / 128, 16);
    moe_mma<0, 512, 256, false><<<g1, 256>>>(x, W1, b1);
    moe_mma<1, 256, 256, false><<<g2, 256>>>(nullptr, W2, b2);
    moe_mma<2, 256, 512, true ><<<g3, 256>>>(nullptr, W3, b3);

    finalize<<<(T_TOK * 512 / 4) / 256, 256>>>(out);
}